// round 14
// baseline (speedup 1.0000x reference)
#include <cuda_runtime.h>

#define Dd  30
#define H1d 15
#define Tt  512
#define Bb  4096
#define GSTR 36   // per-group state stride (floats): 144B -> 16B aligned, disjoint banks

typedef unsigned long long ull;

// scratch: u1 = Wih1*x + b (padded to 32 floats/row), h2 sequence (padded to 32)
__device__ __align__(128) float g_u1[(size_t)Bb * Tt * 32];
__device__ __align__(128) float g_h2[(size_t)Bb * Tt * 32];

__device__ __forceinline__ void fma2(ull& d, ull a, ull b) {
    asm("fma.rn.f32x2 %0, %1, %2, %0;" : "+l"(d) : "l"(a), "l"(b));
}
__device__ __forceinline__ ull packf2(float lo, float hi) {
    ull r; asm("mov.b64 %0, {%1, %2};" : "=l"(r) : "f"(lo), "f"(hi)); return r;
}
__device__ __forceinline__ float2 unpackf2(ull v) {
    float2 r; asm("mov.b64 {%0, %1}, %2;" : "=f"(r.x), "=f"(r.y) : "l"(v)); return r;
}
__device__ __forceinline__ float fast_tanh(float x) {
    x = fminf(15.f, fmaxf(-15.f, x));
    float e = __expf(2.f * x);
    return __fdividef(e - 1.f, e + 1.f);
}

__device__ __forceinline__ float dot30(const float* __restrict__ buf, const ull* Wp) {
    const ulonglong2* vp = (const ulonglong2*)buf;
    ull a0 = 0, a1 = 0;
#pragma unroll
    for (int i = 0; i < 7; i++) {
        ulonglong2 v = vp[i];
        fma2(a0, Wp[2 * i],     v.x);
        fma2(a1, Wp[2 * i + 1], v.y);
    }
    fma2(a0, Wp[14], ((const ull*)buf)[14]);
    float2 f0 = unpackf2(a0), f1 = unpackf2(a1);
    return (f0.x + f0.y) + (f1.x + f1.y);
}
__device__ __forceinline__ float dot16(const float* __restrict__ buf, const ull* Wp) {
    const ulonglong2* vp = (const ulonglong2*)buf;
    ull a0 = 0, a1 = 0;
#pragma unroll
    for (int i = 0; i < 4; i++) {
        ulonglong2 v = vp[i];
        fma2(a0, Wp[2 * i],     v.x);
        fma2(a1, Wp[2 * i + 1], v.y);
    }
    float2 f0 = unpackf2(a0), f1 = unpackf2(a1);
    return (f0.x + f0.y) + (f1.x + f1.y);
}

#define PCH 4    // t-chunks per batch in proj  -> chunk = 128 steps
#define MCH 16   // t-chunks per batch in mlp   -> chunk = 32 steps

// ---------------- Kernel A: u1 = Wih1*x + bih1 + bhh1 (parallel over b AND t) ----------------
__global__ void __launch_bounds__(128)
proj_kernel(const float* __restrict__ x, const float* __restrict__ Wih1,
            const float* __restrict__ bih1, const float* __restrict__ bhh1)
{
    __shared__ __align__(16) float xs[4][2][32];
    const int lane = threadIdx.x & 31;
    const int wrp  = threadIdx.x >> 5;
    const int gid  = blockIdx.x * 4 + wrp;
    const int b    = gid >> 2;
    const int t0   = (gid & 3) * (Tt / PCH);
    const bool rowv = (lane < Dd);

    ull Wp[15];
    const ull* w = (const ull*)(Wih1 + lane * Dd);
#pragma unroll
    for (int i = 0; i < 15; i++) Wp[i] = rowv ? w[i] : 0ull;
    const float bsum = rowv ? (bih1[lane] + bhh1[lane]) : 0.f;

    const float* __restrict__ xb = x + (size_t)b * Tt * Dd + (size_t)t0 * Dd;
    float* __restrict__ ub = g_u1 + (size_t)b * Tt * 32 + (size_t)t0 * 32;
    float (*xbuf)[32] = xs[wrp];

    xbuf[0][lane] = rowv ? __ldg(xb + lane) : 0.f;
    float xn = rowv ? __ldg(xb + Dd + lane) : 0.f;
    __syncwarp();

    for (int t = 0; t < Tt / PCH; t++) {
        const int p = t & 1;
        float u = dot30(xbuf[p], Wp) + bsum;     // exact 0 on lanes >= 30
        ub[t * 32 + lane] = u;
        xbuf[1 - p][lane] = xn;
        xn = (rowv && t + 2 < Tt / PCH) ? __ldg(xb + (size_t)(t + 2) * Dd + lane) : 0.f;
        __syncwarp();
    }
}

// ---------------- Kernel B: skew-pipelined recurrences, 2 batch / warp, 2 rows / lane ----------------
__global__ void __launch_bounds__(32)
recur_kernel(const float* __restrict__ Whh1,
             const float* __restrict__ Wih2, const float* __restrict__ Whh2,
             const float* __restrict__ bih2, const float* __restrict__ bhh2)
{
    __shared__ __align__(16) float h1sm[2][2 * GSTR], h2sm[2][2 * GSTR];
    const int lane = threadIdx.x;
    const int grp  = lane >> 4;          // which batch element of the pair
    const int sub  = lane & 15;          // row-pair index
    const int r0   = 2 * sub;            // owns rows r0, r0+1 (sub==15 -> pad rows 30,31)
    const bool rv  = (sub < 15);

    // 3 matrices x 2 rows x 15 packed f32x2 = 180 regs
    ull W11a[15], W11b[15], W12a[15], W12b[15], W22a[15], W22b[15];
    {
        const ull* a11 = (const ull*)(Whh1 + r0 * Dd);
        const ull* b11 = (const ull*)(Whh1 + (r0 + 1) * Dd);
        const ull* a12 = (const ull*)(Wih2 + r0 * Dd);
        const ull* b12 = (const ull*)(Wih2 + (r0 + 1) * Dd);
        const ull* a22 = (const ull*)(Whh2 + r0 * Dd);
        const ull* b22 = (const ull*)(Whh2 + (r0 + 1) * Dd);
#pragma unroll
        for (int i = 0; i < 15; i++) {
            W11a[i] = rv ? a11[i] : 0ull;  W11b[i] = rv ? b11[i] : 0ull;
            W12a[i] = rv ? a12[i] : 0ull;  W12b[i] = rv ? b12[i] : 0ull;
            W22a[i] = rv ? a22[i] : 0ull;  W22b[i] = rv ? b22[i] : 0ull;
        }
    }
    const float2 bs2 = rv ? make_float2(bih2[r0] + bhh2[r0], bih2[r0 + 1] + bhh2[r0 + 1])
                          : make_float2(0.f, 0.f);

    const int b = blockIdx.x * 2 + grp;
    const float* __restrict__ ub = g_u1 + (size_t)b * Tt * 32;
    float* __restrict__ hb = g_h2 + (size_t)b * Tt * 32;

    for (int i = lane; i < 2 * 2 * GSTR; i += 32) {
        ((float*)h1sm)[i] = 0.f; ((float*)h2sm)[i] = 0.f;
    }
    float2 u1c = *(const float2*)(ub + r0);          // u1[0] (pad cols are 0)
    float2 u1n = *(const float2*)(ub + 32 + r0);     // u1[1]
    __syncwarp();

    // ---- peel s = 0: h1[0] = tanh(u1[0]) ----
    {
        float2 h; h.x = fast_tanh(u1c.x); h.y = fast_tanh(u1c.y);
        *(float2*)&h1sm[0][grp * GSTR + r0] = h;
        u1c = u1n;
        u1n = *(const float2*)(ub + 2 * 32 + r0);
    }
    __syncwarp();

    // ---- hot loop s = 1..511: compute h1[s] and h2[s-1] in one stage ----
    for (int s = 1; s < Tt; s++) {
        const int p = s & 1, q = 1 - p;
        const float* __restrict__ h1q = &h1sm[q][grp * GSTR];   // h1[s-1]
        const float* __restrict__ h2p = &h2sm[p][grp * GSTR];   // h2[s-2]

        ull A = 0, B = 0, C = 0, D = 0, E = 0, F = 0;
#pragma unroll
        for (int i = 0; i < 7; i++) {
            ulonglong2 v = ((const ulonglong2*)h1q)[i];          // h1 row: loaded once, 4 dots
            fma2(A, W11a[2 * i], v.x); fma2(A, W11a[2 * i + 1], v.y);
            fma2(B, W11b[2 * i], v.x); fma2(B, W11b[2 * i + 1], v.y);
            fma2(C, W12a[2 * i], v.x); fma2(C, W12a[2 * i + 1], v.y);
            fma2(D, W12b[2 * i], v.x); fma2(D, W12b[2 * i + 1], v.y);
        }
        {
            ull vl = ((const ull*)h1q)[14];
            fma2(A, W11a[14], vl); fma2(B, W11b[14], vl);
            fma2(C, W12a[14], vl); fma2(D, W12b[14], vl);
        }
#pragma unroll
        for (int i = 0; i < 7; i++) {
            ulonglong2 v = ((const ulonglong2*)h2p)[i];          // h2 row: 2 dots
            fma2(E, W22a[2 * i], v.x); fma2(E, W22a[2 * i + 1], v.y);
            fma2(F, W22b[2 * i], v.x); fma2(F, W22b[2 * i + 1], v.y);
        }
        {
            ull vl = ((const ull*)h2p)[14];
            fma2(E, W22a[14], vl); fma2(F, W22b[14], vl);
        }
        float2 fA = unpackf2(A), fB = unpackf2(B), fC = unpackf2(C);
        float2 fD = unpackf2(D), fE = unpackf2(E), fF = unpackf2(F);
        float2 h1n, h2n;
        h1n.x = fast_tanh((fA.x + fA.y) + u1c.x);
        h1n.y = fast_tanh((fB.x + fB.y) + u1c.y);
        h2n.x = fast_tanh((fC.x + fC.y) + (fE.x + fE.y) + bs2.x);
        h2n.y = fast_tanh((fD.x + fD.y) + (fF.x + fF.y) + bs2.y);

        *(float2*)&h1sm[p][grp * GSTR + r0] = h1n;               // h1[s]
        *(float2*)&h2sm[q][grp * GSTR + r0] = h2n;               // h2[s-1]
        *(float2*)&hb[(size_t)(s - 1) * 32 + r0] = h2n;          // stream out (coalesced .64)

        u1c = u1n;
        u1n = (s + 2 < Tt) ? *(const float2*)(ub + (size_t)(s + 2) * 32 + r0)
                           : make_float2(0.f, 0.f);
        __syncwarp();
    }

    // ---- epilogue: h2[511] from h1[511] (parity 1) and h2[510] (parity 0) ----
    {
        const float* __restrict__ h1q = &h1sm[1][grp * GSTR];
        const float* __restrict__ h2p = &h2sm[0][grp * GSTR];
        ull C = 0, D = 0, E = 0, F = 0;
#pragma unroll
        for (int i = 0; i < 7; i++) {
            ulonglong2 v = ((const ulonglong2*)h1q)[i];
            fma2(C, W12a[2 * i], v.x); fma2(C, W12a[2 * i + 1], v.y);
            fma2(D, W12b[2 * i], v.x); fma2(D, W12b[2 * i + 1], v.y);
        }
        { ull vl = ((const ull*)h1q)[14]; fma2(C, W12a[14], vl); fma2(D, W12b[14], vl); }
#pragma unroll
        for (int i = 0; i < 7; i++) {
            ulonglong2 v = ((const ulonglong2*)h2p)[i];
            fma2(E, W22a[2 * i], v.x); fma2(E, W22a[2 * i + 1], v.y);
            fma2(F, W22b[2 * i], v.x); fma2(F, W22b[2 * i + 1], v.y);
        }
        { ull vl = ((const ull*)h2p)[14]; fma2(E, W22a[14], vl); fma2(F, W22b[14], vl); }
        float2 fC = unpackf2(C), fD = unpackf2(D), fE = unpackf2(E), fF = unpackf2(F);
        float2 h2n;
        h2n.x = fast_tanh((fC.x + fC.y) + (fE.x + fE.y) + bs2.x);
        h2n.y = fast_tanh((fD.x + fD.y) + (fF.x + fF.y) + bs2.y);
        *(float2*)&hb[(size_t)(Tt - 1) * 32 + r0] = h2n;
    }
}

// ---------------- Kernel C: MLP head (parallel over b AND t) ----------------
__global__ void __launch_bounds__(128)
mlp_kernel(const float* __restrict__ W1, const float* __restrict__ b1,
           const float* __restrict__ W2, const float* __restrict__ b2,
           const float* __restrict__ W3, const float* __restrict__ b3,
           float* __restrict__ out)
{
    __shared__ __align__(16) float h2s[4][2][32], z1s[4][32], ys[4][32];
    const int lane = threadIdx.x & 31;
    const int wrp  = threadIdx.x >> 5;
    const int gid  = blockIdx.x * 4 + wrp;
    const int b    = gid >> 4;
    const int t0   = (gid & 15) * (Tt / MCH);
    const bool mlpv = (lane < H1d);

    ull W1p[15], W2p[8];
    {
        const ull* w1 = (const ull*)(W1 + lane * Dd);
#pragma unroll
        for (int i = 0; i < 15; i++) W1p[i] = mlpv ? w1[i] : 0ull;
#pragma unroll
        for (int i = 0; i < 7; i++)
            W2p[i] = mlpv ? packf2(W2[lane * H1d + 2 * i], W2[lane * H1d + 2 * i + 1]) : 0ull;
        W2p[7] = mlpv ? packf2(W2[lane * H1d + 14], 0.f) : 0ull;
    }
    const float W3r = mlpv ? W3[lane] : 0.f;
    const float b1r = mlpv ? b1[lane] : 0.f;
    const float b2r = mlpv ? b2[lane] : 0.f;
    const float b3v = b3[0];

    const float* __restrict__ hrow = g_h2 + (size_t)b * Tt * 32 + (size_t)t0 * 32;
    float* __restrict__ ob = out + (size_t)b * Tt + t0;

    float (*hbuf)[32] = h2s[wrp];
    hbuf[0][lane] = __ldg(hrow + lane);            // coalesced row prefetch
    float hn = __ldg(hrow + 32 + lane);
    __syncwarp();

    for (int i = 0; i < Tt / MCH; i++) {
        const int p = i & 1;
        float z1 = fast_tanh(dot30(hbuf[p], W1p) + b1r);   // exact 0 on lanes >= 15
        z1s[wrp][lane] = z1;
        hbuf[1 - p][lane] = hn;
        __syncwarp();
        float z2 = fast_tanh(dot16(z1s[wrp], W2p) + b2r);
        float s = W3r * z2;
#pragma unroll
        for (int off = 8; off >= 1; off >>= 1)
            s += __shfl_xor_sync(0xffffffffu, s, off);
        if (lane == 0) ys[wrp][i] = s + b3v;
        hn = (i + 2 < Tt / MCH) ? __ldg(hrow + (size_t)(i + 2) * 32 + lane) : 0.f;
        __syncwarp();
    }
    ob[lane] = ys[wrp][lane];
}

extern "C" void kernel_launch(void* const* d_in, const int* in_sizes, int n_in,
                              void* d_out, int out_size)
{
    const float* x    = (const float*)d_in[0];
    const float* Wih1 = (const float*)d_in[1];
    const float* Whh1 = (const float*)d_in[2];
    const float* bih1 = (const float*)d_in[3];
    const float* bhh1 = (const float*)d_in[4];
    const float* Wih2 = (const float*)d_in[5];
    const float* Whh2 = (const float*)d_in[6];
    const float* bih2 = (const float*)d_in[7];
    const float* bhh2 = (const float*)d_in[8];
    const float* W1   = (const float*)d_in[9];
    const float* b1   = (const float*)d_in[10];
    const float* W2   = (const float*)d_in[11];
    const float* b2   = (const float*)d_in[12];
    const float* W3   = (const float*)d_in[13];
    const float* b3   = (const float*)d_in[14];

    int B = in_sizes[0] / (Tt * Dd);   // 4096
    proj_kernel<<<B * PCH / 4, 128>>>(x, Wih1, bih1, bhh1);
    recur_kernel<<<B / 2, 32>>>(Whh1, Wih2, Whh2, bih2, bhh2);
    mlp_kernel<<<B * MCH / 4, 128>>>(W1, b1, W2, b2, W3, b3, (float*)d_out);
}

// round 15
// speedup vs baseline: 1.3438x; 1.3438x over previous
#include <cuda_runtime.h>

#define Dd  30
#define H1d 15
#define Tt  512

typedef unsigned long long ull;

__device__ __forceinline__ void fma2(ull& d, ull a, ull b) {
    asm("fma.rn.f32x2 %0, %1, %2, %0;" : "+l"(d) : "l"(a), "l"(b));
}
__device__ __forceinline__ ull packf2(float lo, float hi) {
    ull r; asm("mov.b64 %0, {%1, %2};" : "=l"(r) : "f"(lo), "f"(hi)); return r;
}
__device__ __forceinline__ float2 unpackf2(ull v) {
    float2 r; asm("mov.b64 {%0, %1}, %2;" : "=f"(r.x), "=f"(r.y) : "l"(v)); return r;
}
__device__ __forceinline__ float fast_tanh(float x) {
    x = fminf(15.f, fmaxf(-15.f, x));
    float e = __expf(2.f * x);
    return __fdividef(e - 1.f, e + 1.f);
}

// two 30-elem dots sharing ONE load of buf
__device__ __forceinline__ float2 dual30(const float* __restrict__ buf,
                                         const ull* Wa, const ull* Wb) {
    const ulonglong2* vp = (const ulonglong2*)buf;
    ull a0 = 0, a1 = 0, b0 = 0, b1 = 0;
#pragma unroll
    for (int i = 0; i < 7; i++) {
        ulonglong2 v = vp[i];
        fma2(a0, Wa[2 * i],     v.x);
        fma2(b0, Wb[2 * i],     v.x);
        fma2(a1, Wa[2 * i + 1], v.y);
        fma2(b1, Wb[2 * i + 1], v.y);
    }
    ull vl = ((const ull*)buf)[14];
    fma2(a0, Wa[14], vl);
    fma2(b0, Wb[14], vl);
    float2 fa0 = unpackf2(a0), fa1 = unpackf2(a1);
    float2 fb0 = unpackf2(b0), fb1 = unpackf2(b1);
    return make_float2((fa0.x + fa0.y) + (fa1.x + fa1.y),
                       (fb0.x + fb0.y) + (fb1.x + fb1.y));
}
__device__ __forceinline__ float dot30(const float* __restrict__ buf, const ull* Wp) {
    const ulonglong2* vp = (const ulonglong2*)buf;
    ull a0 = 0, a1 = 0;
#pragma unroll
    for (int i = 0; i < 7; i++) {
        ulonglong2 v = vp[i];
        fma2(a0, Wp[2 * i],     v.x);
        fma2(a1, Wp[2 * i + 1], v.y);
    }
    fma2(a0, Wp[14], ((const ull*)buf)[14]);
    float2 f0 = unpackf2(a0), f1 = unpackf2(a1);
    return (f0.x + f0.y) + (f1.x + f1.y);
}
__device__ __forceinline__ float dot16(const float* __restrict__ buf, const ull* Wp) {
    const ulonglong2* vp = (const ulonglong2*)buf;
    ull a0 = 0, a1 = 0;
#pragma unroll
    for (int i = 0; i < 4; i++) {
        ulonglong2 v = vp[i];
        fma2(a0, Wp[2 * i],     v.x);
        fma2(a1, Wp[2 * i + 1], v.y);
    }
    float2 f0 = unpackf2(a0), f1 = unpackf2(a1);
    return (f0.x + f0.y) + (f1.x + f1.y);
}

// Fused: RNN1 + RNN2 + MLP head in a 4-deep software pipeline, 1 syncwarp/step.
// Stage s computes: h1[s], h2[s-1], z1[s-2], z2[s-3], y[s-3].
__global__ void __launch_bounds__(32)
rnn_fused_pipe(const float* __restrict__ x,
               const float* __restrict__ Wih1, const float* __restrict__ Whh1,
               const float* __restrict__ bih1, const float* __restrict__ bhh1,
               const float* __restrict__ Wih2, const float* __restrict__ Whh2,
               const float* __restrict__ bih2, const float* __restrict__ bhh2,
               const float* __restrict__ W1,  const float* __restrict__ b1,
               const float* __restrict__ W2,  const float* __restrict__ b2,
               const float* __restrict__ W3,  const float* __restrict__ b3,
               float* __restrict__ out)
{
    __shared__ __align__(16) float xs[2][32], h1sm[2][32], h2sm[2][32], z1sm[2][32];
    __shared__ __align__(16) float ys[32];

    const int  lane = threadIdx.x;
    const int  b    = blockIdx.x;
    const bool rowv = (lane < Dd);
    const bool mlpv = (lane < H1d);

    // ---- weights in registers: lane j = row j (pad rows exact 0) ----
    ull Wi1[15], Wh1[15], Wi2[15], Wh2[15], W1p[15], W2p[8];
    {
        const ull* a = (const ull*)(Wih1 + lane * Dd);
        const ull* c = (const ull*)(Whh1 + lane * Dd);
        const ull* d = (const ull*)(Wih2 + lane * Dd);
        const ull* e = (const ull*)(Whh2 + lane * Dd);
        const ull* f = (const ull*)(W1   + lane * Dd);
#pragma unroll
        for (int i = 0; i < 15; i++) {
            Wi1[i] = rowv ? a[i] : 0ull;
            Wh1[i] = rowv ? c[i] : 0ull;
            Wi2[i] = rowv ? d[i] : 0ull;
            Wh2[i] = rowv ? e[i] : 0ull;
            W1p[i] = mlpv ? f[i] : 0ull;
        }
#pragma unroll
        for (int i = 0; i < 7; i++)
            W2p[i] = mlpv ? packf2(W2[lane * H1d + 2 * i], W2[lane * H1d + 2 * i + 1]) : 0ull;
        W2p[7] = mlpv ? packf2(W2[lane * H1d + 14], 0.f) : 0ull;
    }
    const float bs1r = rowv ? (bih1[lane] + bhh1[lane]) : 0.f;
    const float bs2r = rowv ? (bih2[lane] + bhh2[lane]) : 0.f;
    const float b1r  = mlpv ? b1[lane] : 0.f;
    const float b2r  = mlpv ? b2[lane] : 0.f;
    const float W3r  = mlpv ? W3[lane] : 0.f;
    const float b3v  = b3[0];

    const float* __restrict__ xb = x + (size_t)b * Tt * Dd;
    float* __restrict__ ob = out + (size_t)b * Tt;

    // ---- init: zero rings; prime x pipeline (xs[0]=x[0], xn1=x[1], xn2=x[2]) ----
    xs[1][lane] = 0.f;
    h1sm[0][lane] = 0.f; h1sm[1][lane] = 0.f;
    h2sm[0][lane] = 0.f; h2sm[1][lane] = 0.f;
    z1sm[0][lane] = 0.f; z1sm[1][lane] = 0.f;
    xs[0][lane] = rowv ? __ldg(xb + lane) : 0.f;
    float xn1 = rowv ? __ldg(xb + Dd + lane) : 0.f;
    float xn2 = rowv ? __ldg(xb + 2 * Dd + lane) : 0.f;
    __syncwarp();

#pragma unroll 2
    for (int s = 0; s < Tt + 3; s++) {
        const int p = s & 1, q = 1 - p;

        // 4 independent dot chains (deep ILP); dual dots share row loads
        float2 dA = dual30(h1sm[q], Wh1, Wi2);   // h1[s-1] -> (Whh1, Wih2)
        float2 dB = dual30(h2sm[p], Wh2, W1p);   // h2[s-2] -> (Whh2, W1)
        float  dC = dot30 (xs[p],   Wi1);        // x[s]    -> Wih1
        float  dD = dot16 (z1sm[q], W2p);        // z1[s-3] -> W2

        float h1n = fast_tanh(dA.x + dC + bs1r);          // h1[s]
        float h2n = fast_tanh(dA.y + dB.x + bs2r);        // h2[s-1]
        float z1n = fast_tanh(dB.y + b1r);                // z1[s-2]
        float z2n = fast_tanh(dD + b2r);                  // z2[s-3]

        // y[s-3] = W3·z2 + b3 (butterfly over 16; lanes>=15 contribute exact 0)
        float yv = W3r * z2n;
#pragma unroll
        for (int off = 8; off >= 1; off >>= 1)
            yv += __shfl_xor_sync(0xffffffffu, yv, off);
        if (lane == 0) ys[(s + 29) & 31] = yv + b3v;      // index (s-3)&31

        h1sm[p][lane] = h1n;
        if (s >= 1) h2sm[q][lane] = h2n;                  // keep h2[-1] == 0
        z1sm[p][lane] = z1n;
        xs[q][lane] = xn1;                                // stage x[s+1]
        xn1 = xn2;
        xn2 = (rowv && s + 3 < Tt) ? __ldg(xb + (size_t)(s + 3) * Dd + lane) : 0.f;
        __syncwarp();

        // coalesced flush of y[s-34 .. s-3] every 32 steps
        if ((s & 31) == 2 && s >= 34)
            ob[(s - 34) + lane] = ys[lane];
    }
}

extern "C" void kernel_launch(void* const* d_in, const int* in_sizes, int n_in,
                              void* d_out, int out_size)
{
    const float* x    = (const float*)d_in[0];
    const float* Wih1 = (const float*)d_in[1];
    const float* Whh1 = (const float*)d_in[2];
    const float* bih1 = (const float*)d_in[3];
    const float* bhh1 = (const float*)d_in[4];
    const float* Wih2 = (const float*)d_in[5];
    const float* Whh2 = (const float*)d_in[6];
    const float* bih2 = (const float*)d_in[7];
    const float* bhh2 = (const float*)d_in[8];
    const float* W1   = (const float*)d_in[9];
    const float* b1   = (const float*)d_in[10];
    const float* W2   = (const float*)d_in[11];
    const float* b2   = (const float*)d_in[12];
    const float* W3   = (const float*)d_in[13];
    const float* b3   = (const float*)d_in[14];

    int B = in_sizes[0] / (Tt * Dd);   // 4096
    rnn_fused_pipe<<<B, 32>>>(x, Wih1, Whh1, bih1, bhh1,
                              Wih2, Whh2, bih2, bhh2,
                              W1, b1, W2, b2, W3, b3,
                              (float*)d_out);
}